// round 10
// baseline (speedup 1.0000x reference)
#include <cuda_runtime.h>
#include <math.h>
#include <limits.h>
#include <stdint.h>

#define NN 50000
#define NP 50048          // NN padded to multiple of 128
#define FF 128
#define CC 512
#define EE 800000
#define HH 256

#define OFF_NEWX 0
#define OFF_ADJ  (CC*FF)
#define OFF_BATCH (OFF_ADJ + CC*CC)
#define OFF_S    (OFF_BATCH + CC)

// weight slab offsets (elements) in g_Wth/g_Wtl
#define WOFF1 0
#define WOFF2 (128*256)
#define WOFF3 (128*256+256*256)
#define WTOT  (128*256+256*256+256*512)

// ---------------- device scratch (static, no allocations) ----------------
static __device__ float g_h[(size_t)NP*CC];     // GEMM outputs (padded rows); y for layers 1-2
static __device__ float g_Ah[(size_t)NP*HH];    // tf32-hi aggregated features (padded)
static __device__ float g_Al[(size_t)NP*HH];    // tf32-lo aggregated features (padded)
static __device__ float g_Wth[WTOT];            // transposed tf32-hi weights (all layers)
static __device__ float g_Wtl[WTOT];            // transposed tf32-lo weights
static __device__ int   g_rowptr[NN+1];
static __device__ int   g_deg[NN];
static __device__ int   g_cursor[NN];
static __device__ int   g_csrsrc[EE];
static __device__ float g_inv[NP];              // padded (pad entries stay 0)
static __device__ float g_hs[NN];               // hs, later overwritten with z=invs*hs
static __device__ float g_invs[NN];
static __device__ int   g_cluster[NN];
static __device__ unsigned long long g_segpack[CC];
static __device__ int   g_cintra[CC];
static __device__ int   g_part[256];

// ---------------- helpers ----------------
__device__ __forceinline__ int fenc(float f){ int i=__float_as_int(f); return i<0 ? (i^0x7FFFFFFF) : i; }
__device__ __forceinline__ float fdec(int i){ return __int_as_float(i<0 ? (i^0x7FFFFFFF) : i); }

__device__ __forceinline__ float to_tf32(float a){
  float r; asm("cvt.rna.tf32.f32 %0,%1;":"=f"(r):"f"(a)); return r;
}

__device__ __forceinline__ uint32_t smem_u32(const void* p){
  uint32_t a; asm("{ .reg .u64 t; cvta.to.shared.u64 t, %1; cvt.u32.u64 %0, t; }":"=r"(a):"l"(p)); return a;
}

__device__ __forceinline__ void cpa16f(uint32_t s, const void* g){
  asm volatile("cp.async.ca.shared.global [%0], [%1], 16;"::"r"(s),"l"(g));
}
#define CPA_COMMIT() asm volatile("cp.async.commit_group;")
#define CPA_WAIT0()  asm volatile("cp.async.wait_group 0;":::"memory")

// ldmatrix x4: each m8n8.b16 tile == 8x4 tf32 tile with exact mma fragment lane mapping
#define LDSM4(d, addr) asm volatile( \
    "ldmatrix.sync.aligned.m8n8.x4.shared.b16 {%0,%1,%2,%3},[%4];" \
    : "=r"((d)[0]),"=r"((d)[1]),"=r"((d)[2]),"=r"((d)[3]) : "r"(addr))

// mma.sync m16n8k8 tf32: D += A*B (row.col), accumulate in place
__device__ __forceinline__ void mma8(float* c, const uint32_t* a, uint32_t b0, uint32_t b1){
  asm volatile(
    "mma.sync.aligned.m16n8k8.row.col.f32.tf32.tf32.f32 "
    "{%0,%1,%2,%3},{%4,%5,%6,%7},{%8,%9},{%0,%1,%2,%3};"
    : "+f"(c[0]),"+f"(c[1]),"+f"(c[2]),"+f"(c[3])
    : "r"(a[0]),"r"(a[1]),"r"(a[2]),"r"(a[3]),"r"(b0),"r"(b1));
}

// ---------------- setup kernels ----------------
__global__ void k_init(float* __restrict__ out){
  int i=blockIdx.x*blockDim.x+threadIdx.x;
  if(i<NN) g_deg[i]=0;
  if(i<CC){ g_cintra[i]=0; g_segpack[i]=0ull; }
  if(i<CC*CC+CC) out[OFF_ADJ+i]=0.f;
}

__global__ void k_deg(const int* __restrict__ dst){
  int e=blockIdx.x*blockDim.x+threadIdx.x;
  if(e<EE) atomicAdd(&g_deg[dst[e]],1);
}

// 3-phase exclusive scan of g_deg -> g_rowptr
__global__ void k_scan1(){
  int b=blockIdx.x, t=threadIdx.x, i=b*256+t;
  int v=(i<NN)?g_deg[i]:0;
  int x=v;
  #pragma unroll
  for(int off=1;off<32;off<<=1){
    int y=__shfl_up_sync(0xffffffffu,x,off);
    if((t&31)>=off) x+=y;
  }
  __shared__ int ws[8];
  if((t&31)==31) ws[t>>5]=x;
  __syncthreads();
  if(t==0){ int s=0; for(int j=0;j<8;j++){int tmp=ws[j]; ws[j]=s; s+=tmp;} g_part[b]=s; }
  __syncthreads();
  if(i<NN) g_rowptr[i]= x - v + ws[t>>5];
}
// parallel block scan of g_part
__global__ void k_scan2(int nblk){
  int t=threadIdx.x;
  int v=(t<nblk)?g_part[t]:0;
  int x=v;
  #pragma unroll
  for(int off=1;off<32;off<<=1){
    int y=__shfl_up_sync(0xffffffffu,x,off);
    if((t&31)>=off) x+=y;
  }
  __shared__ int ws[8];
  if((t&31)==31) ws[t>>5]=x;
  __syncthreads();
  if(t==0){ int s=0; for(int j=0;j<8;j++){int tmp=ws[j]; ws[j]=s; s+=tmp;} ws[0]=0; /*unused*/ }
  __syncthreads();
  // recompute warp bases serially stored: redo to keep simple
  __shared__ int wb[8];
  if((t&31)==31) wb[t>>5]=x;
  __syncthreads();
  if(t==0){ int s=0; for(int j=0;j<8;j++){int tmp=wb[j]; wb[j]=s; s+=tmp;} }
  __syncthreads();
  int excl = x - v + wb[t>>5];
  if(t<nblk) g_part[t]=excl;
  if(t==nblk-1) g_rowptr[NN]=excl+v;
}
// fused: finalize rowptr + cursor + inv
__global__ void k_scan3p(){
  int i=blockIdx.x*blockDim.x+threadIdx.x;
  if(i>=NN) return;
  int v=g_rowptr[i]+g_part[i>>8];
  g_rowptr[i]=v;
  g_cursor[i]=v;
  g_inv[i]=rsqrtf((float)g_deg[i]+1.0f);
}

__global__ void k_scatter(const int* __restrict__ src, const int* __restrict__ dst){
  int e=blockIdx.x*blockDim.x+threadIdx.x;
  if(e>=EE) return;
  int d=dst[e];
  int p=atomicAdd(&g_cursor[d],1);
  g_csrsrc[p]=src[e];
}

// ---------------- layer-1 aggregation (x input, needs inv[src]) + fused hs ----------------
__global__ void k_agg1(const float* __restrict__ h, float* __restrict__ ah, float* __restrict__ al,
                       const float* __restrict__ Wsm){
  int warp=blockIdx.x*(blockDim.x>>5) + (threadIdx.x>>5);
  int lane=threadIdx.x&31;
  if(warp>=NN) return;
  const float4* h4=(const float4*)h;
  size_t base=(size_t)warp*32;
  float wi=g_inv[warp];
  float4 q=h4[base+lane];
  {
    float4 w=((const float4*)Wsm)[lane];
    float d=q.x*w.x+q.y*w.y+q.z*w.z+q.w*w.w;
    #pragma unroll
    for(int off=16;off>0;off>>=1) d+=__shfl_down_sync(0xffffffffu,d,off);
    if(lane==0) g_hs[warp]=d;
  }
  float4 acc; acc.x=q.x*wi; acc.y=q.y*wi; acc.z=q.z*wi; acc.w=q.w*wi;
  int s=g_rowptr[warp], e=g_rowptr[warp+1];
  for(int t=s;t<e;t++){
    int src=g_csrsrc[t];
    float ws=g_inv[src];
    float4 r=h4[(size_t)src*32+lane];
    acc.x=fmaf(r.x,ws,acc.x); acc.y=fmaf(r.y,ws,acc.y);
    acc.z=fmaf(r.z,ws,acc.z); acc.w=fmaf(r.w,ws,acc.w);
  }
  float f[4]={acc.x*wi, acc.y*wi, acc.z*wi, acc.w*wi};
  float4 hi,lo;
  hi.x=to_tf32(f[0]); lo.x=to_tf32(f[0]-hi.x);
  hi.y=to_tf32(f[1]); lo.y=to_tf32(f[1]-hi.y);
  hi.z=to_tf32(f[2]); lo.z=to_tf32(f[2]-hi.z);
  hi.w=to_tf32(f[3]); lo.w=to_tf32(f[3]-hi.w);
  ((float4*)ah)[base+lane]=hi;
  ((float4*)al)[base+lane]=lo;
}

// ---------------- layers 2/3 aggregation over pre-scaled y (no inv[src] loads) ----------------
__global__ void k_aggy(const float* __restrict__ y, float* __restrict__ ah, float* __restrict__ al){
  int warp=blockIdx.x*(blockDim.x>>5) + (threadIdx.x>>5);
  int lane=threadIdx.x&31;
  if(warp>=NN) return;
  const float4* y4=(const float4*)y;
  size_t base=(size_t)warp*64;
  float wi=g_inv[warp];
  float4 acc0=y4[base+lane], acc1=y4[base+32+lane];
  int s=g_rowptr[warp], e=g_rowptr[warp+1];
  for(int t=s;t<e;t++){
    int src=g_csrsrc[t];
    const float4* r=y4+(size_t)src*64;
    float4 q0=r[lane], q1=r[32+lane];
    acc0.x+=q0.x; acc0.y+=q0.y; acc0.z+=q0.z; acc0.w+=q0.w;
    acc1.x+=q1.x; acc1.y+=q1.y; acc1.z+=q1.z; acc1.w+=q1.w;
  }
  float4* ah4=(float4*)ah; float4* al4=(float4*)al;
  float f0[4]={acc0.x*wi,acc0.y*wi,acc0.z*wi,acc0.w*wi};
  float f1[4]={acc1.x*wi,acc1.y*wi,acc1.z*wi,acc1.w*wi};
  float4 hi,lo;
  hi.x=to_tf32(f0[0]); lo.x=to_tf32(f0[0]-hi.x);
  hi.y=to_tf32(f0[1]); lo.y=to_tf32(f0[1]-hi.y);
  hi.z=to_tf32(f0[2]); lo.z=to_tf32(f0[2]-hi.z);
  hi.w=to_tf32(f0[3]); lo.w=to_tf32(f0[3]-hi.w);
  ah4[base+lane]=hi; al4[base+lane]=lo;
  hi.x=to_tf32(f1[0]); lo.x=to_tf32(f1[0]-hi.x);
  hi.y=to_tf32(f1[1]); lo.y=to_tf32(f1[1]-hi.y);
  hi.z=to_tf32(f1[2]); lo.z=to_tf32(f1[2]-hi.z);
  hi.w=to_tf32(f1[3]); lo.w=to_tf32(f1[3]-hi.w);
  ah4[base+32+lane]=hi; al4[base+32+lane]=lo;
}

// transpose + split all three weight matrices in one kernel
__global__ void k_wsplit3(const float* __restrict__ W1, const float* __restrict__ W2,
                          const float* __restrict__ W3){
  int idx=blockIdx.x*blockDim.x+threadIdx.x;
  if(idx>=WTOT) return;
  const float* W; int Min,Kout,off,li;
  if(idx<WOFF2){ W=W1; Min=128; Kout=256; off=WOFF1; li=idx; }
  else if(idx<WOFF3){ W=W2; Min=256; Kout=256; off=WOFF2; li=idx-WOFF2; }
  else { W=W3; Min=256; Kout=512; off=WOFF3; li=idx-WOFF3; }
  int m=li/Kout, nk=li-m*Kout;
  float w=W[li];
  float hi=to_tf32(w);
  float lo=to_tf32(w-hi);
  g_Wth[off+nk*Min+m]=hi;
  g_Wtl[off+nk*Min+m]=lo;
}

// ---------------- tf32 split-3 mma.sync GEMM with ldmatrix fragment loads ----------------
// CTA tile 128(m) x 128(n); 8 warps 4m x 2n; warp tile 32x64; K chunks of 32.
// YOUT: multiply relu output by g_inv[row] (produces y for next layer's aggregation)
#define PAD 36
#define CHF (128*PAD)          // floats per matrix slab
#define CHB (CHF*4)            // bytes per matrix slab
template<bool YOUT>
__global__ __launch_bounds__(256,2) void k_mma(
    const float* __restrict__ Ah, const float* __restrict__ Al,
    const float* __restrict__ Bh, const float* __restrict__ Bl,
    const float* __restrict__ bias, float* __restrict__ C,
    int Min, int Kout)
{
  extern __shared__ float sm[];
  int tid=threadIdx.x, lane=tid&31, wid=tid>>5;
  int wm = wid&3, wn = wid>>2;         // 4x2 warp grid
  int bm = blockIdx.y*128, bn = blockIdx.x*128;

  uint32_t s_base = smem_u32(sm);
  uint32_t sAh=s_base, sAl=s_base+CHB, sBh=s_base+2*CHB, sBl=s_base+3*CHB;

  float acc[2][8][4];
  #pragma unroll
  for(int a=0;a<2;a++)
    #pragma unroll
    for(int b=0;b<8;b++)
      #pragma unroll
      for(int c=0;c<4;c++) acc[a][b][c]=0.f;

  // ldmatrix per-lane base offsets (bytes within a slab)
  int g=lane>>3, r=lane&7;
  uint32_t a_off[2], b_off[4];
  #pragma unroll
  for(int mf=0;mf<2;mf++)
    a_off[mf]=(uint32_t)((wm*32+mf*16+(g&1)*8+r)*PAD + (g>>1)*4)*4;
  #pragma unroll
  for(int p=0;p<4;p++)
    b_off[p]=(uint32_t)((wn*64+(2*p+(g>>1))*8+r)*PAD + (g&1)*4)*4;

  int r_ld = tid>>3, c_ld=(tid&7)*4;   // cp.async coords

  int nch = Min>>5;
  for(int ch=0; ch<nch; ch++){
    int k0=ch<<5;
    #pragma unroll
    for(int it=0;it<4;it++){
      int rr = r_ld + it*32;
      uint32_t soff=(uint32_t)(rr*PAD+c_ld)*4;
      cpa16f(sAh+soff, &Ah[(size_t)(bm+rr)*Min+k0+c_ld]);
      cpa16f(sAl+soff, &Al[(size_t)(bm+rr)*Min+k0+c_ld]);
      cpa16f(sBh+soff, &Bh[(size_t)(bn+rr)*Min+k0+c_ld]);
      cpa16f(sBl+soff, &Bl[(size_t)(bn+rr)*Min+k0+c_ld]);
    }
    CPA_COMMIT();
    CPA_WAIT0();
    __syncthreads();

    #pragma unroll
    for(int ks=0;ks<4;ks++){
      uint32_t ko = (uint32_t)ks*32;   // 8 floats
      uint32_t afh[2][4], afl[2][4];
      LDSM4(afh[0], sAh + a_off[0] + ko);
      LDSM4(afh[1], sAh + a_off[1] + ko);
      LDSM4(afl[0], sAl + a_off[0] + ko);
      LDSM4(afl[1], sAl + a_off[1] + ko);
      #pragma unroll
      for(int p=0;p<4;p++){
        uint32_t bh4[4], bl4[4];
        LDSM4(bh4, sBh + b_off[p] + ko);
        LDSM4(bl4, sBl + b_off[p] + ko);
        #pragma unroll
        for(int q=0;q<2;q++){
          int nf=2*p+q;
          uint32_t bh0=bh4[q*2], bh1=bh4[q*2+1];
          uint32_t bl0=bl4[q*2], bl1=bl4[q*2+1];
          #pragma unroll
          for(int mf=0;mf<2;mf++){
            mma8(acc[mf][nf], afh[mf], bh0, bh1);
            mma8(acc[mf][nf], afh[mf], bl0, bl1);
            mma8(acc[mf][nf], afl[mf], bh0, bh1);
          }
        }
      }
    }
    __syncthreads();
  }

  // epilogue: bias + relu (+ optional inv scaling), unconditional float2 stores
  #pragma unroll
  for(int mf=0;mf<2;mf++){
    int row0 = bm + wm*32 + mf*16 + (lane>>2);
    float i0=1.f, i1=1.f;
    if(YOUT){ i0=g_inv[row0]; i1=g_inv[row0+8]; }
    #pragma unroll
    for(int nf=0;nf<8;nf++){
      int col = bn + wn*64 + nf*8 + (lane&3)*2;
      float b0v=bias[col], b1v=bias[col+1];
      float2 v0, v1;
      v0.x=fmaxf(acc[mf][nf][0]+b0v,0.f); v0.y=fmaxf(acc[mf][nf][1]+b1v,0.f);
      v1.x=fmaxf(acc[mf][nf][2]+b0v,0.f); v1.y=fmaxf(acc[mf][nf][3]+b1v,0.f);
      if(YOUT){ v0.x*=i0; v0.y*=i0; v1.x*=i1; v1.y*=i1; }
      *(float2*)&C[(size_t)row0*Kout+col]=v0;
      *(float2*)&C[(size_t)(row0+8)*Kout+col]=v1;
    }
  }
}
#define MMA_SMEM (4*CHB)

// ---------------- softmax + argmax (warp per row of 512, float4 IO) ----------------
__global__ void k_softmax(const float* __restrict__ h, float* __restrict__ S){
  int warp=blockIdx.x*(blockDim.x>>5)+(threadIdx.x>>5);
  int lane=threadIdx.x&31;
  if(warp>=NN) return;
  const float4* row4=(const float4*)(h+(size_t)warp*CC);
  float4 v[4];
  #pragma unroll
  for(int c=0;c<4;c++) v[c]=row4[c*32+lane];
  float m=-3.4e38f; int am=0;
  #pragma unroll
  for(int c=0;c<4;c++){
    float* f=(float*)&v[c];
    #pragma unroll
    for(int j=0;j<4;j++){
      int col=c*128+lane*4+j;
      if(f[j]>m){m=f[j];am=col;}
    }
  }
  #pragma unroll
  for(int off=16;off>0;off>>=1){
    float om=__shfl_down_sync(0xffffffffu,m,off);
    int   oa=__shfl_down_sync(0xffffffffu,am,off);
    if(om>m || (om==m && oa<am)){m=om;am=oa;}
  }
  m=__shfl_sync(0xffffffffu,m,0);
  am=__shfl_sync(0xffffffffu,am,0);
  float s=0.f;
  #pragma unroll
  for(int c=0;c<4;c++){
    float* f=(float*)&v[c];
    #pragma unroll
    for(int j=0;j<4;j++){ f[j]=expf(f[j]-m); s+=f[j]; }
  }
  #pragma unroll
  for(int off=16;off>0;off>>=1) s+=__shfl_down_sync(0xffffffffu,s,off);
  s=__shfl_sync(0xffffffffu,s,0);
  float invs=1.f/s;
  float4* so4=(float4*)(S+(size_t)warp*CC);
  #pragma unroll
  for(int c=0;c<4;c++){
    float* f=(float*)&v[c];
    #pragma unroll
    for(int j=0;j<4;j++) f[j]*=invs;
    so4[c*32+lane]=v[c];
  }
  if(lane==0) g_cluster[warp]=am;
}

// ---------------- score branch ----------------
// intra-degree + invs + z=invs*hs (overwrites g_hs)
__global__ void k_degs(){
  int i=blockIdx.x*blockDim.x+threadIdx.x;
  if(i>=NN) return;
  int ci=g_cluster[i];
  int s=g_rowptr[i], e=g_rowptr[i+1], cnt=0;
  #pragma unroll 4
  for(int t=s;t<e;t++) cnt += (g_cluster[g_csrsrc[t]]==ci) ? 1 : 0;
  float w=rsqrtf((float)cnt+1.0f);
  g_invs[i]=w;
  g_hs[i]=w*g_hs[i];
  if(cnt>0) atomicAdd(&g_cintra[ci],cnt);
}

// score + packed segmax/argmin + coarse adjacency, one CSR pass
__global__ void k_score(const float* __restrict__ bs, float* __restrict__ out){
  int i=blockIdx.x*blockDim.x+threadIdx.x;
  if(i>=NN) return;
  int ci=g_cluster[i];
  bool iok = g_cintra[ci]>0;
  int s=g_rowptr[i], e=g_rowptr[i+1];
  float sum=0.f;
  #pragma unroll 4
  for(int t=s;t<e;t++){
    int sn=g_csrsrc[t];
    int cs=g_cluster[sn];
    if(cs==ci) sum += g_hs[sn];                       // z = invs*hs
    else if(iok && g_cintra[cs]>0) out[OFF_ADJ + cs*CC + ci]=1.0f;
  }
  float w=g_invs[i];
  float sc=tanhf(w*(sum + g_hs[i]) + bs[0]);          // self term: w*z_i == w^2*hs_i
  unsigned int key=((unsigned int)fenc(sc))^0x80000000u;
  unsigned long long pack=((unsigned long long)key<<32)|(unsigned int)(NN-1-i);
  atomicMax(&g_segpack[ci], pack);
}

// ---------------- outputs ----------------
__global__ void k_newx(const float* __restrict__ x, float* __restrict__ out){
  int c=blockIdx.x;
  int t=threadIdx.x;
  __shared__ float alpha; __shared__ int idx;
  if(t==0){
    unsigned long long p=g_segpack[c];
    int sidx = NN-1-(int)(unsigned int)(p&0xffffffffu);
    idx = min(max(sidx,0), NN-1);
    float sc = fdec((int)((unsigned int)(p>>32)^0x80000000u));
    alpha = (g_cintra[c]>0) ? sc : 0.f;
  }
  __syncthreads();
  out[OFF_NEWX + c*FF + t] = x[(size_t)idx*FF + t]*alpha;
}

// ---------------- launch ----------------
extern "C" void kernel_launch(void* const* d_in, const int* in_sizes, int n_in,
                              void* d_out, int out_size)
{
  const float* x  =(const float*)d_in[0];
  const int*   ei =(const int*)  d_in[1];
  const float* W1 =(const float*)d_in[3];
  const float* b1 =(const float*)d_in[4];
  const float* W2 =(const float*)d_in[5];
  const float* b2 =(const float*)d_in[6];
  const float* W3 =(const float*)d_in[7];
  const float* b3 =(const float*)d_in[8];
  const float* Wsm=(const float*)d_in[9];
  const float* bs =(const float*)d_in[10];
  float* out=(float*)d_out;

  const int* srcp=ei;
  const int* dstp=ei+EE;

  float *p_h,*p_ah,*p_al,*p_wh,*p_wl;
  cudaGetSymbolAddress((void**)&p_h,  g_h);
  cudaGetSymbolAddress((void**)&p_ah, g_Ah);
  cudaGetSymbolAddress((void**)&p_al, g_Al);
  cudaGetSymbolAddress((void**)&p_wh, g_Wth);
  cudaGetSymbolAddress((void**)&p_wl, g_Wtl);

  cudaFuncSetAttribute(k_mma<true>,  cudaFuncAttributeMaxDynamicSharedMemorySize, MMA_SMEM);
  cudaFuncSetAttribute(k_mma<false>, cudaFuncAttributeMaxDynamicSharedMemorySize, MMA_SMEM);

  const int TB=256;
  const int gN=(NN+TB-1)/TB;            // 196
  const int gE=(EE+TB-1)/TB;
  const int gW=(NN+7)/8;
  const int gM=NP/128;                  // 391
  const int gI=(CC*CC+CC+TB-1)/TB;

  // graph prep
  k_init<<<gI,TB>>>(out);
  k_deg<<<gE,TB>>>(dstp);
  k_scan1<<<gN,TB>>>();
  k_scan2<<<1,256>>>(gN);
  k_scan3p<<<gN,TB>>>();
  k_scatter<<<gE,TB>>>(srcp,dstp);
  k_wsplit3<<<(WTOT+TB-1)/TB,TB>>>(W1,W2,W3);

  // layer 1: F=128 -> 256 (hs fused; epilogue emits y1 = inv*relu)
  k_agg1<<<gW,TB>>>(x,p_ah,p_al,Wsm);
  k_mma<true><<<dim3(2,gM),256,MMA_SMEM>>>(p_ah,p_al,p_wh+WOFF1,p_wl+WOFF1,b1,p_h,128,256);

  // layer 2: 256 -> 256 (gather over y1; epilogue emits y2)
  k_aggy<<<gW,TB>>>(p_h,p_ah,p_al);
  k_mma<true><<<dim3(2,gM),256,MMA_SMEM>>>(p_ah,p_al,p_wh+WOFF2,p_wl+WOFF2,b2,p_h,256,256);

  // layer 3: 256 -> 512 (gather over y2; plain h3 out for softmax)
  k_aggy<<<gW,TB>>>(p_h,p_ah,p_al);
  k_mma<false><<<dim3(4,gM),256,MMA_SMEM>>>(p_ah,p_al,p_wh+WOFF3,p_wl+WOFF3,b3,p_h,256,512);

  // softmax S + hard cluster assignment
  k_softmax<<<gW,TB>>>(p_h, out+OFF_S);

  // score branch
  k_degs<<<gN,TB>>>();
  k_score<<<gN,TB>>>(bs,out);

  // pooled features
  k_newx<<<CC,FF>>>(x,out);
}

// round 11
// speedup vs baseline: 1.0756x; 1.0756x over previous
#include <cuda_runtime.h>
#include <math.h>
#include <limits.h>
#include <stdint.h>

#define NN 50000
#define NP 50048          // NN padded to multiple of 128
#define FF 128
#define CC 512
#define EE 800000
#define HH 256

#define OFF_NEWX 0
#define OFF_ADJ  (CC*FF)
#define OFF_BATCH (OFF_ADJ + CC*CC)
#define OFF_S    (OFF_BATCH + CC)

// weight slab offsets (elements) in g_Wth/g_Wtl
#define WOFF1 0
#define WOFF2 (128*256)
#define WOFF3 (128*256+256*256)
#define WTOT  (128*256+256*256+256*512)

// ---------------- device scratch (static, no allocations) ----------------
static __device__ float g_h[(size_t)NP*CC];     // GEMM outputs (padded rows)
static __device__ float g_Ah[(size_t)NP*HH];    // tf32-hi aggregated features (padded)
static __device__ float g_Al[(size_t)NP*HH];    // tf32-lo aggregated features (padded)
static __device__ float g_Wth[WTOT];            // transposed tf32-hi weights (all layers)
static __device__ float g_Wtl[WTOT];            // transposed tf32-lo weights
static __device__ int   g_rowptr[NN+1];
static __device__ int   g_deg[NN];
static __device__ int   g_cursor[NN];
static __device__ int   g_csrsrc[EE];
static __device__ float g_inv[NN];
static __device__ float g_hs[NN];               // hs, later overwritten with z=invs*hs
static __device__ float g_invs[NN];
static __device__ int   g_cluster[NN];
static __device__ unsigned long long g_segpack[CC];
static __device__ int   g_cintra[CC];
static __device__ int   g_part[256];

// ---------------- helpers ----------------
__device__ __forceinline__ int fenc(float f){ int i=__float_as_int(f); return i<0 ? (i^0x7FFFFFFF) : i; }
__device__ __forceinline__ float fdec(int i){ return __int_as_float(i<0 ? (i^0x7FFFFFFF) : i); }

__device__ __forceinline__ float to_tf32(float a){
  float r; asm("cvt.rna.tf32.f32 %0,%1;":"=f"(r):"f"(a)); return r;
}

__device__ __forceinline__ uint32_t smem_u32(const void* p){
  uint32_t a; asm("{ .reg .u64 t; cvta.to.shared.u64 t, %1; cvt.u32.u64 %0, t; }":"=r"(a):"l"(p)); return a;
}

__device__ __forceinline__ void cpa16f(uint32_t s, const void* g){
  asm volatile("cp.async.ca.shared.global [%0], [%1], 16;"::"r"(s),"l"(g));
}
#define CPA_COMMIT() asm volatile("cp.async.commit_group;")
#define CPA_WAIT0()  asm volatile("cp.async.wait_group 0;":::"memory")

// ldmatrix x4: each m8n8.b16 tile == 8x4 tf32 tile with exact mma fragment lane mapping
#define LDSM4(d, addr) asm volatile( \
    "ldmatrix.sync.aligned.m8n8.x4.shared.b16 {%0,%1,%2,%3},[%4];" \
    : "=r"((d)[0]),"=r"((d)[1]),"=r"((d)[2]),"=r"((d)[3]) : "r"(addr))

// mma.sync m16n8k8 tf32: D += A*B (row.col), accumulate in place
__device__ __forceinline__ void mma8(float* c, const uint32_t* a, uint32_t b0, uint32_t b1){
  asm volatile(
    "mma.sync.aligned.m16n8k8.row.col.f32.tf32.tf32.f32 "
    "{%0,%1,%2,%3},{%4,%5,%6,%7},{%8,%9},{%0,%1,%2,%3};"
    : "+f"(c[0]),"+f"(c[1]),"+f"(c[2]),"+f"(c[3])
    : "r"(a[0]),"r"(a[1]),"r"(a[2]),"r"(a[3]),"r"(b0),"r"(b1));
}

// ---------------- setup kernels ----------------
__global__ void k_init(float* __restrict__ out){
  int i=blockIdx.x*blockDim.x+threadIdx.x;
  if(i<NN) g_deg[i]=0;
  if(i<CC){ g_cintra[i]=0; g_segpack[i]=0ull; }
  if(i<CC*CC+CC) out[OFF_ADJ+i]=0.f;
}

__global__ void k_deg(const int* __restrict__ dst){
  int e=blockIdx.x*blockDim.x+threadIdx.x;
  if(e<EE) atomicAdd(&g_deg[dst[e]],1);
}

// 3-phase exclusive scan of g_deg -> g_rowptr
__global__ void k_scan1(){
  int b=blockIdx.x, t=threadIdx.x, i=b*256+t;
  int v=(i<NN)?g_deg[i]:0;
  int x=v;
  #pragma unroll
  for(int off=1;off<32;off<<=1){
    int y=__shfl_up_sync(0xffffffffu,x,off);
    if((t&31)>=off) x+=y;
  }
  __shared__ int ws[8];
  if((t&31)==31) ws[t>>5]=x;
  __syncthreads();
  if(t==0){ int s=0; for(int j=0;j<8;j++){int tmp=ws[j]; ws[j]=s; s+=tmp;} g_part[b]=s; }
  __syncthreads();
  if(i<NN) g_rowptr[i]= x - v + ws[t>>5];
}
// parallel scan of g_part (nblk <= 256)
__global__ void k_scan2(int nblk){
  int t=threadIdx.x;
  int v=(t<nblk)?g_part[t]:0;
  int x=v;
  #pragma unroll
  for(int off=1;off<32;off<<=1){
    int y=__shfl_up_sync(0xffffffffu,x,off);
    if((t&31)>=off) x+=y;
  }
  __shared__ int wb[8];
  if((t&31)==31) wb[t>>5]=x;
  __syncthreads();
  if(t==0){ int s=0; for(int j=0;j<8;j++){int tmp=wb[j]; wb[j]=s; s+=tmp;} }
  __syncthreads();
  int excl = x - v + wb[t>>5];
  if(t<nblk) g_part[t]=excl;
  if(t==nblk-1) g_rowptr[NN]=excl+v;
}
// fused: finalize rowptr + cursor + inv
__global__ void k_scan3p(){
  int i=blockIdx.x*blockDim.x+threadIdx.x;
  if(i>=NN) return;
  int v=g_rowptr[i]+g_part[i>>8];
  g_rowptr[i]=v;
  g_cursor[i]=v;
  g_inv[i]=rsqrtf((float)g_deg[i]+1.0f);
}

__global__ void k_scatter(const int* __restrict__ src, const int* __restrict__ dst){
  int e=blockIdx.x*blockDim.x+threadIdx.x;
  if(e>=EE) return;
  int d=dst[e];
  int p=atomicAdd(&g_cursor[d],1);
  g_csrsrc[p]=src[e];
}

// ---------------- aggregation with fused inv scaling + tf32 split (+ optional hs) ----------------
// agg[i] = inv_i*(inv_i*h[i] + sum_{e:dst=i} inv_src*h[src]); hi/lo tf32 split output
template<int V, bool HS>
__global__ void k_agg(const float* __restrict__ h, float* __restrict__ ah, float* __restrict__ al,
                      const float* __restrict__ Wsm){
  int warp=blockIdx.x*(blockDim.x>>5) + (threadIdx.x>>5);
  int lane=threadIdx.x&31;
  if(warp>=NN) return;
  const float4* h4=(const float4*)h;
  size_t base=(size_t)warp*(32*V);
  float wi=g_inv[warp];
  float4 acc[V];
  #pragma unroll
  for(int v=0;v<V;v++){
    float4 q=h4[base+v*32+lane];
    if(HS && v==0){
      float4 w=((const float4*)Wsm)[lane];
      float d=q.x*w.x+q.y*w.y+q.z*w.z+q.w*w.w;
      #pragma unroll
      for(int off=16;off>0;off>>=1) d+=__shfl_down_sync(0xffffffffu,d,off);
      if(lane==0) g_hs[warp]=d;
    }
    acc[v].x=q.x*wi; acc[v].y=q.y*wi; acc[v].z=q.z*wi; acc[v].w=q.w*wi;
  }
  int s=g_rowptr[warp], e=g_rowptr[warp+1];
  for(int t=s;t<e;t++){
    int src=g_csrsrc[t];
    float ws=g_inv[src];
    const float4* r=h4+(size_t)src*(32*V);
    #pragma unroll
    for(int v=0;v<V;v++){
      float4 q=r[v*32+lane];
      acc[v].x=fmaf(q.x,ws,acc[v].x);
      acc[v].y=fmaf(q.y,ws,acc[v].y);
      acc[v].z=fmaf(q.z,ws,acc[v].z);
      acc[v].w=fmaf(q.w,ws,acc[v].w);
    }
  }
  float4* ah4=(float4*)ah; float4* al4=(float4*)al;
  #pragma unroll
  for(int v=0;v<V;v++){
    float f[4]={acc[v].x*wi, acc[v].y*wi, acc[v].z*wi, acc[v].w*wi};
    float4 hi,lo;
    hi.x=to_tf32(f[0]); lo.x=to_tf32(f[0]-hi.x);
    hi.y=to_tf32(f[1]); lo.y=to_tf32(f[1]-hi.y);
    hi.z=to_tf32(f[2]); lo.z=to_tf32(f[2]-hi.z);
    hi.w=to_tf32(f[3]); lo.w=to_tf32(f[3]-hi.w);
    ah4[base+v*32+lane]=hi;
    al4[base+v*32+lane]=lo;
  }
}

// transpose + split all three weight matrices in one kernel
__global__ void k_wsplit3(const float* __restrict__ W1, const float* __restrict__ W2,
                          const float* __restrict__ W3){
  int idx=blockIdx.x*blockDim.x+threadIdx.x;
  if(idx>=WTOT) return;
  const float* W; int Min,Kout,off,li;
  if(idx<WOFF2){ W=W1; Min=128; Kout=256; off=WOFF1; li=idx; }
  else if(idx<WOFF3){ W=W2; Min=256; Kout=256; off=WOFF2; li=idx-WOFF2; }
  else { W=W3; Min=256; Kout=512; off=WOFF3; li=idx-WOFF3; }
  int m=li/Kout, nk=li-m*Kout;
  float w=W[li];
  float hi=to_tf32(w);
  float lo=to_tf32(w-hi);
  g_Wth[off+nk*Min+m]=hi;
  g_Wtl[off+nk*Min+m]=lo;
}

// ---------------- tf32 split-3 mma.sync GEMM with ldmatrix fragment loads ----------------
// CTA tile 128(m) x 128(n); 8 warps 4m x 2n; warp tile 32x64; K chunks of 32.
#define PAD 36
#define CHF (128*PAD)          // floats per matrix slab
#define CHB (CHF*4)            // bytes per matrix slab
__global__ __launch_bounds__(256,2) void k_mma(
    const float* __restrict__ Ah, const float* __restrict__ Al,
    const float* __restrict__ Bh, const float* __restrict__ Bl,
    const float* __restrict__ bias, float* __restrict__ C,
    int Min, int Kout)
{
  extern __shared__ float sm[];
  int tid=threadIdx.x, lane=tid&31, wid=tid>>5;
  int wm = wid&3, wn = wid>>2;         // 4x2 warp grid
  int bm = blockIdx.y*128, bn = blockIdx.x*128;

  uint32_t s_base = smem_u32(sm);
  uint32_t sAh=s_base, sAl=s_base+CHB, sBh=s_base+2*CHB, sBl=s_base+3*CHB;

  float acc[2][8][4];
  #pragma unroll
  for(int a=0;a<2;a++)
    #pragma unroll
    for(int b=0;b<8;b++)
      #pragma unroll
      for(int c=0;c<4;c++) acc[a][b][c]=0.f;

  // ldmatrix per-lane base offsets (bytes within a slab)
  int g=lane>>3, r=lane&7;
  uint32_t a_off[2], b_off[4];
  #pragma unroll
  for(int mf=0;mf<2;mf++)
    a_off[mf]=(uint32_t)((wm*32+mf*16+(g&1)*8+r)*PAD + (g>>1)*4)*4;
  #pragma unroll
  for(int p=0;p<4;p++)
    b_off[p]=(uint32_t)((wn*64+(2*p+(g>>1))*8+r)*PAD + (g&1)*4)*4;

  int r_ld = tid>>3, c_ld=(tid&7)*4;   // cp.async coords

  int nch = Min>>5;
  for(int ch=0; ch<nch; ch++){
    int k0=ch<<5;
    #pragma unroll
    for(int it=0;it<4;it++){
      int rr = r_ld + it*32;
      uint32_t soff=(uint32_t)(rr*PAD+c_ld)*4;
      cpa16f(sAh+soff, &Ah[(size_t)(bm+rr)*Min+k0+c_ld]);
      cpa16f(sAl+soff, &Al[(size_t)(bm+rr)*Min+k0+c_ld]);
      cpa16f(sBh+soff, &Bh[(size_t)(bn+rr)*Min+k0+c_ld]);
      cpa16f(sBl+soff, &Bl[(size_t)(bn+rr)*Min+k0+c_ld]);
    }
    CPA_COMMIT();
    CPA_WAIT0();
    __syncthreads();

    #pragma unroll
    for(int ks=0;ks<4;ks++){
      uint32_t ko = (uint32_t)ks*32;   // 8 floats
      uint32_t afh[2][4], afl[2][4];
      LDSM4(afh[0], sAh + a_off[0] + ko);
      LDSM4(afh[1], sAh + a_off[1] + ko);
      LDSM4(afl[0], sAl + a_off[0] + ko);
      LDSM4(afl[1], sAl + a_off[1] + ko);
      #pragma unroll
      for(int p=0;p<4;p++){
        uint32_t bh4[4], bl4[4];
        LDSM4(bh4, sBh + b_off[p] + ko);
        LDSM4(bl4, sBl + b_off[p] + ko);
        #pragma unroll
        for(int q=0;q<2;q++){
          int nf=2*p+q;
          uint32_t bh0=bh4[q*2], bh1=bh4[q*2+1];
          uint32_t bl0=bl4[q*2], bl1=bl4[q*2+1];
          #pragma unroll
          for(int mf=0;mf<2;mf++){
            mma8(acc[mf][nf], afh[mf], bh0, bh1);
            mma8(acc[mf][nf], afh[mf], bl0, bl1);
            mma8(acc[mf][nf], afl[mf], bh0, bh1);
          }
        }
      }
    }
    __syncthreads();
  }

  // epilogue: bias + relu, unconditional float2 stores (C is row-padded)
  #pragma unroll
  for(int mf=0;mf<2;mf++){
    int row0 = bm + wm*32 + mf*16 + (lane>>2);
    #pragma unroll
    for(int nf=0;nf<8;nf++){
      int col = bn + wn*64 + nf*8 + (lane&3)*2;
      float b0v=bias[col], b1v=bias[col+1];
      float2 v0; v0.x=fmaxf(acc[mf][nf][0]+b0v,0.f); v0.y=fmaxf(acc[mf][nf][1]+b1v,0.f);
      *(float2*)&C[(size_t)row0*Kout+col]=v0;
      float2 v1; v1.x=fmaxf(acc[mf][nf][2]+b0v,0.f); v1.y=fmaxf(acc[mf][nf][3]+b1v,0.f);
      *(float2*)&C[(size_t)(row0+8)*Kout+col]=v1;
    }
  }
}
#define MMA_SMEM (4*CHB)

// ---------------- softmax + argmax (warp per row of 512, float4 IO) ----------------
__global__ void k_softmax(const float* __restrict__ h, float* __restrict__ S){
  int warp=blockIdx.x*(blockDim.x>>5)+(threadIdx.x>>5);
  int lane=threadIdx.x&31;
  if(warp>=NN) return;
  const float4* row4=(const float4*)(h+(size_t)warp*CC);
  float4 v[4];
  #pragma unroll
  for(int c=0;c<4;c++) v[c]=row4[c*32+lane];
  float m=-3.4e38f; int am=0;
  #pragma unroll
  for(int c=0;c<4;c++){
    float* f=(float*)&v[c];
    #pragma unroll
    for(int j=0;j<4;j++){
      int col=c*128+lane*4+j;
      if(f[j]>m){m=f[j];am=col;}
    }
  }
  #pragma unroll
  for(int off=16;off>0;off>>=1){
    float om=__shfl_down_sync(0xffffffffu,m,off);
    int   oa=__shfl_down_sync(0xffffffffu,am,off);
    if(om>m || (om==m && oa<am)){m=om;am=oa;}
  }
  m=__shfl_sync(0xffffffffu,m,0);
  am=__shfl_sync(0xffffffffu,am,0);
  float s=0.f;
  #pragma unroll
  for(int c=0;c<4;c++){
    float* f=(float*)&v[c];
    #pragma unroll
    for(int j=0;j<4;j++){ f[j]=expf(f[j]-m); s+=f[j]; }
  }
  #pragma unroll
  for(int off=16;off>0;off>>=1) s+=__shfl_down_sync(0xffffffffu,s,off);
  s=__shfl_sync(0xffffffffu,s,0);
  float invs=1.f/s;
  float4* so4=(float4*)(S+(size_t)warp*CC);
  #pragma unroll
  for(int c=0;c<4;c++){
    float* f=(float*)&v[c];
    #pragma unroll
    for(int j=0;j<4;j++) f[j]*=invs;
    so4[c*32+lane]=v[c];
  }
  if(lane==0) g_cluster[warp]=am;
}

// ---------------- score branch ----------------
// intra-degree + invs + z=invs*hs (overwrites g_hs)
__global__ void k_degs(){
  int i=blockIdx.x*blockDim.x+threadIdx.x;
  if(i>=NN) return;
  int ci=g_cluster[i];
  int s=g_rowptr[i], e=g_rowptr[i+1], cnt=0;
  for(int t=s;t<e;t++) cnt += (g_cluster[g_csrsrc[t]]==ci) ? 1 : 0;
  float w=rsqrtf((float)cnt+1.0f);
  g_invs[i]=w;
  g_hs[i]=w*g_hs[i];
  if(cnt>0) atomicAdd(&g_cintra[ci],cnt);
}

// score + packed segmax/argmin + coarse adjacency, one CSR pass
__global__ void k_score(const float* __restrict__ bs, float* __restrict__ out){
  int i=blockIdx.x*blockDim.x+threadIdx.x;
  if(i>=NN) return;
  int ci=g_cluster[i];
  bool iok = g_cintra[ci]>0;
  int s=g_rowptr[i], e=g_rowptr[i+1];
  float sum=0.f;
  for(int t=s;t<e;t++){
    int sn=g_csrsrc[t];
    int cs=g_cluster[sn];
    if(cs==ci) sum += g_hs[sn];                       // z = invs*hs
    else if(iok && g_cintra[cs]>0) out[OFF_ADJ + cs*CC + ci]=1.0f;
  }
  float w=g_invs[i];
  float sc=tanhf(w*(sum + g_hs[i]) + bs[0]);          // self term: w*z_i == w^2*hs_i
  unsigned int key=((unsigned int)fenc(sc))^0x80000000u;
  unsigned long long pack=((unsigned long long)key<<32)|(unsigned int)(NN-1-i);
  atomicMax(&g_segpack[ci], pack);
}

// ---------------- outputs ----------------
__global__ void k_newx(const float* __restrict__ x, float* __restrict__ out){
  int c=blockIdx.x;
  int t=threadIdx.x;
  __shared__ float alpha; __shared__ int idx;
  if(t==0){
    unsigned long long p=g_segpack[c];
    int sidx = NN-1-(int)(unsigned int)(p&0xffffffffu);
    idx = min(max(sidx,0), NN-1);
    float sc = fdec((int)((unsigned int)(p>>32)^0x80000000u));
    alpha = (g_cintra[c]>0) ? sc : 0.f;
  }
  __syncthreads();
  out[OFF_NEWX + c*FF + t] = x[(size_t)idx*FF + t]*alpha;
}

// ---------------- launch ----------------
extern "C" void kernel_launch(void* const* d_in, const int* in_sizes, int n_in,
                              void* d_out, int out_size)
{
  const float* x  =(const float*)d_in[0];
  const int*   ei =(const int*)  d_in[1];
  const float* W1 =(const float*)d_in[3];
  const float* b1 =(const float*)d_in[4];
  const float* W2 =(const float*)d_in[5];
  const float* b2 =(const float*)d_in[6];
  const float* W3 =(const float*)d_in[7];
  const float* b3 =(const float*)d_in[8];
  const float* Wsm=(const float*)d_in[9];
  const float* bs =(const float*)d_in[10];
  float* out=(float*)d_out;

  const int* srcp=ei;
  const int* dstp=ei+EE;

  float *p_h,*p_ah,*p_al,*p_wh,*p_wl;
  cudaGetSymbolAddress((void**)&p_h,  g_h);
  cudaGetSymbolAddress((void**)&p_ah, g_Ah);
  cudaGetSymbolAddress((void**)&p_al, g_Al);
  cudaGetSymbolAddress((void**)&p_wh, g_Wth);
  cudaGetSymbolAddress((void**)&p_wl, g_Wtl);

  cudaFuncSetAttribute(k_mma, cudaFuncAttributeMaxDynamicSharedMemorySize, MMA_SMEM);

  const int TB=256;
  const int gN=(NN+TB-1)/TB;            // 196
  const int gE=(EE+TB-1)/TB;
  const int gW=(NN+7)/8;
  const int gM=NP/128;                  // 391
  const int gI=(CC*CC+CC+TB-1)/TB;

  // graph prep
  k_init<<<gI,TB>>>(out);
  k_deg<<<gE,TB>>>(dstp);
  k_scan1<<<gN,TB>>>();
  k_scan2<<<1,256>>>(gN);
  k_scan3p<<<gN,TB>>>();
  k_scatter<<<gE,TB>>>(srcp,dstp);
  k_wsplit3<<<(WTOT+TB-1)/TB,TB>>>(W1,W2,W3);

  // layer 1: F=128 -> 256 (hs fused into agg)
  k_agg<1,true><<<gW,TB>>>(x,p_ah,p_al,Wsm);
  k_mma<<<dim3(2,gM),256,MMA_SMEM>>>(p_ah,p_al,p_wh+WOFF1,p_wl+WOFF1,b1,p_h,128,256);

  // layer 2: 256 -> 256
  k_agg<2,false><<<gW,TB>>>(p_h,p_ah,p_al,Wsm);
  k_mma<<<dim3(2,gM),256,MMA_SMEM>>>(p_ah,p_al,p_wh+WOFF2,p_wl+WOFF2,b2,p_h,256,256);

  // layer 3: 256 -> 512
  k_agg<2,false><<<gW,TB>>>(p_h,p_ah,p_al,Wsm);
  k_mma<<<dim3(4,gM),256,MMA_SMEM>>>(p_ah,p_al,p_wh+WOFF3,p_wl+WOFF3,b3,p_h,256,512);

  // softmax S + hard cluster assignment
  k_softmax<<<gW,TB>>>(p_h, out+OFF_S);

  // score branch (score+segreduce+adj fused)
  k_degs<<<gN,TB>>>();
  k_score<<<gN,TB>>>(bs,out);

  // pooled features
  k_newx<<<CC,FF>>>(x,out);
}

// round 12
// speedup vs baseline: 1.4154x; 1.3159x over previous
#include <cuda_runtime.h>
#include <cuda_fp16.h>
#include <math.h>
#include <limits.h>
#include <stdint.h>

#define NN 50000
#define NP 50048          // NN padded to multiple of 128
#define FF 128
#define CC 512
#define EE 800000
#define HH 256

#define OFF_NEWX 0
#define OFF_ADJ  (CC*FF)
#define OFF_BATCH (OFF_ADJ + CC*CC)
#define OFF_S    (OFF_BATCH + CC)

// weight slab offsets (elements) in g_Wth/g_Wtl
#define WOFF1 0
#define WOFF2 (128*256)
#define WOFF3 (128*256+256*256)
#define WTOT  (128*256+256*256+256*512)

// ---------------- device scratch (static, no allocations) ----------------
static __device__ float  g_h[(size_t)NP*CC];     // GEMM outputs (padded rows)
static __device__ __half g_Ahh[(size_t)NP*HH];   // fp16-hi aggregated features
static __device__ __half g_All[(size_t)NP*HH];   // fp16-lo aggregated features
static __device__ __half g_Wth[WTOT];            // transposed fp16-hi weights (all layers)
static __device__ __half g_Wtl[WTOT];            // transposed fp16-lo weights
static __device__ int    g_rowptr[NN+1];
static __device__ int    g_deg[NN];
static __device__ int    g_cursor[NN];
static __device__ int    g_csrsrc[EE];
static __device__ float  g_inv[NN];
static __device__ float  g_hs[NN];               // hs, later overwritten with z=invs*hs
static __device__ float  g_invs[NN];
static __device__ int    g_cluster[NN];
static __device__ unsigned long long g_segpack[CC];
static __device__ int    g_cintra[CC];
static __device__ int    g_part[256];

// ---------------- helpers ----------------
__device__ __forceinline__ int fenc(float f){ int i=__float_as_int(f); return i<0 ? (i^0x7FFFFFFF) : i; }
__device__ __forceinline__ float fdec(int i){ return __int_as_float(i<0 ? (i^0x7FFFFFFF) : i); }

__device__ __forceinline__ uint32_t smem_u32(const void* p){
  uint32_t a; asm("{ .reg .u64 t; cvta.to.shared.u64 t, %1; cvt.u32.u64 %0, t; }":"=r"(a):"l"(p)); return a;
}

__device__ __forceinline__ void cpa16f(uint32_t s, const void* g){
  asm volatile("cp.async.ca.shared.global [%0], [%1], 16;"::"r"(s),"l"(g));
}
#define CPA_COMMIT() asm volatile("cp.async.commit_group;")
#define CPA_WAIT0()  asm volatile("cp.async.wait_group 0;":::"memory")

#define LDSM4(d, addr) asm volatile( \
    "ldmatrix.sync.aligned.m8n8.x4.shared.b16 {%0,%1,%2,%3},[%4];" \
    : "=r"((d)[0]),"=r"((d)[1]),"=r"((d)[2]),"=r"((d)[3]) : "r"(addr))

// mma.sync m16n8k16 fp16 -> fp32: D += A*B (row.col)
__device__ __forceinline__ void mma16(float* c, const uint32_t* a, uint32_t b0, uint32_t b1){
  asm volatile(
    "mma.sync.aligned.m16n8k16.row.col.f32.f16.f16.f32 "
    "{%0,%1,%2,%3},{%4,%5,%6,%7},{%8,%9},{%0,%1,%2,%3};"
    : "+f"(c[0]),"+f"(c[1]),"+f"(c[2]),"+f"(c[3])
    : "r"(a[0]),"r"(a[1]),"r"(a[2]),"r"(a[3]),"r"(b0),"r"(b1));
}

// fp16 hi/lo split of an fp32 value
__device__ __forceinline__ void h_split(float f, __half& hi, __half& lo){
  hi=__float2half_rn(f);
  lo=__float2half_rn(f-__half2float(hi));
}

// ---------------- setup kernels ----------------
__global__ void k_init(float* __restrict__ out){
  int i=blockIdx.x*blockDim.x+threadIdx.x;
  if(i<NN) g_deg[i]=0;
  if(i<CC){ g_cintra[i]=0; g_segpack[i]=0ull; }
  if(i<CC*CC+CC) out[OFF_ADJ+i]=0.f;
}

__global__ void k_deg(const int* __restrict__ dst){
  int e=blockIdx.x*blockDim.x+threadIdx.x;
  if(e<EE) atomicAdd(&g_deg[dst[e]],1);
}

// 3-phase exclusive scan of g_deg -> g_rowptr
__global__ void k_scan1(){
  int b=blockIdx.x, t=threadIdx.x, i=b*256+t;
  int v=(i<NN)?g_deg[i]:0;
  int x=v;
  #pragma unroll
  for(int off=1;off<32;off<<=1){
    int y=__shfl_up_sync(0xffffffffu,x,off);
    if((t&31)>=off) x+=y;
  }
  __shared__ int ws[8];
  if((t&31)==31) ws[t>>5]=x;
  __syncthreads();
  if(t==0){ int s=0; for(int j=0;j<8;j++){int tmp=ws[j]; ws[j]=s; s+=tmp;} g_part[b]=s; }
  __syncthreads();
  if(i<NN) g_rowptr[i]= x - v + ws[t>>5];
}
__global__ void k_scan2(int nblk){
  int t=threadIdx.x;
  int v=(t<nblk)?g_part[t]:0;
  int x=v;
  #pragma unroll
  for(int off=1;off<32;off<<=1){
    int y=__shfl_up_sync(0xffffffffu,x,off);
    if((t&31)>=off) x+=y;
  }
  __shared__ int wb[8];
  if((t&31)==31) wb[t>>5]=x;
  __syncthreads();
  if(t==0){ int s=0; for(int j=0;j<8;j++){int tmp=wb[j]; wb[j]=s; s+=tmp;} }
  __syncthreads();
  int excl = x - v + wb[t>>5];
  if(t<nblk) g_part[t]=excl;
  if(t==nblk-1) g_rowptr[NN]=excl+v;
}
__global__ void k_scan3p(){
  int i=blockIdx.x*blockDim.x+threadIdx.x;
  if(i>=NN) return;
  int v=g_rowptr[i]+g_part[i>>8];
  g_rowptr[i]=v;
  g_cursor[i]=v;
  g_inv[i]=rsqrtf((float)g_deg[i]+1.0f);
}

__global__ void k_scatter(const int* __restrict__ src, const int* __restrict__ dst){
  int e=blockIdx.x*blockDim.x+threadIdx.x;
  if(e>=EE) return;
  int d=dst[e];
  int p=atomicAdd(&g_cursor[d],1);
  g_csrsrc[p]=src[e];
}

// ---------------- aggregation with fused inv scaling + fp16 split (+ optional hs) ----------------
template<int V, bool HS>
__global__ void k_agg(const float* __restrict__ h, __half* __restrict__ ah, __half* __restrict__ al,
                      const float* __restrict__ Wsm){
  int warp=blockIdx.x*(blockDim.x>>5) + (threadIdx.x>>5);
  int lane=threadIdx.x&31;
  if(warp>=NN) return;
  const float4* h4=(const float4*)h;
  size_t base=(size_t)warp*(32*V);
  float wi=g_inv[warp];
  float4 acc[V];
  #pragma unroll
  for(int v=0;v<V;v++){
    float4 q=h4[base+v*32+lane];
    if(HS && v==0){
      float4 w=((const float4*)Wsm)[lane];
      float d=q.x*w.x+q.y*w.y+q.z*w.z+q.w*w.w;
      #pragma unroll
      for(int off=16;off>0;off>>=1) d+=__shfl_down_sync(0xffffffffu,d,off);
      if(lane==0) g_hs[warp]=d;
    }
    acc[v].x=q.x*wi; acc[v].y=q.y*wi; acc[v].z=q.z*wi; acc[v].w=q.w*wi;
  }
  int s=g_rowptr[warp], e=g_rowptr[warp+1];
  for(int t=s;t<e;t++){
    int src=g_csrsrc[t];
    float ws=g_inv[src];
    const float4* r=h4+(size_t)src*(32*V);
    #pragma unroll
    for(int v=0;v<V;v++){
      float4 q=r[v*32+lane];
      acc[v].x=fmaf(q.x,ws,acc[v].x);
      acc[v].y=fmaf(q.y,ws,acc[v].y);
      acc[v].z=fmaf(q.z,ws,acc[v].z);
      acc[v].w=fmaf(q.w,ws,acc[v].w);
    }
  }
  #pragma unroll
  for(int v=0;v<V;v++){
    float f[4]={acc[v].x*wi, acc[v].y*wi, acc[v].z*wi, acc[v].w*wi};
    __half hv[4], lv[4];
    h_split(f[0],hv[0],lv[0]);
    h_split(f[1],hv[1],lv[1]);
    h_split(f[2],hv[2],lv[2]);
    h_split(f[3],hv[3],lv[3]);
    size_t off=(size_t)warp*(128*V) + v*128 + lane*4;
    *(uint2*)&ah[off]=*(uint2*)hv;
    *(uint2*)&al[off]=*(uint2*)lv;
  }
}

// transpose + split all three weight matrices (fp16 hi/lo)
__global__ void k_wsplit3(const float* __restrict__ W1, const float* __restrict__ W2,
                          const float* __restrict__ W3){
  int idx=blockIdx.x*blockDim.x+threadIdx.x;
  if(idx>=WTOT) return;
  const float* W; int Min,Kout,off,li;
  if(idx<WOFF2){ W=W1; Min=128; Kout=256; off=WOFF1; li=idx; }
  else if(idx<WOFF3){ W=W2; Min=256; Kout=256; off=WOFF2; li=idx-WOFF2; }
  else { W=W3; Min=256; Kout=512; off=WOFF3; li=idx-WOFF3; }
  int m=li/Kout, nk=li-m*Kout;
  __half hi,lo;
  h_split(W[li],hi,lo);
  g_Wth[off+nk*Min+m]=hi;
  g_Wtl[off+nk*Min+m]=lo;
}

// ---------------- fp16 split-3 mma.sync GEMM (m16n8k16) with ldmatrix ----------------
// CTA tile 128(m) x 128(n); 8 warps 4m x 2n; warp tile 32x64; K chunks of 32 (2 ksteps of 16).
#define PADH 40               // halves per smem row (80B stride: 16B-aligned, conflict-free)
#define CHH (128*PADH)        // halves per slab
#define CHB2 (CHH*2)          // bytes per slab
__global__ __launch_bounds__(256,2) void k_mma(
    const __half* __restrict__ Ah, const __half* __restrict__ Al,
    const __half* __restrict__ Bh, const __half* __restrict__ Bl,
    const float* __restrict__ bias, float* __restrict__ C,
    int Min, int Kout)
{
  extern __shared__ __half smh[];
  int tid=threadIdx.x, lane=tid&31, wid=tid>>5;
  int wm = wid&3, wn = wid>>2;         // 4x2 warp grid
  int bm = blockIdx.y*128, bn = blockIdx.x*128;

  uint32_t s_base = smem_u32(smh);
  uint32_t sAh=s_base, sAl=s_base+CHB2, sBh=s_base+2*CHB2, sBl=s_base+3*CHB2;

  float acc[2][8][4];
  #pragma unroll
  for(int a=0;a<2;a++)
    #pragma unroll
    for(int b=0;b<8;b++)
      #pragma unroll
      for(int c=0;c<4;c++) acc[a][b][c]=0.f;

  // ldmatrix per-lane base offsets (bytes within a slab)
  int g=lane>>3, lr=lane&7;
  uint32_t a_off[2], b_off[4];
  #pragma unroll
  for(int mf=0;mf<2;mf++)
    a_off[mf]=(uint32_t)((wm*32+mf*16+(g&1)*8+lr)*PADH + (g>>1)*8)*2;
  #pragma unroll
  for(int p=0;p<4;p++)
    b_off[p]=(uint32_t)((wn*64+p*16+(g>>1)*8+lr)*PADH + (g&1)*8)*2;

  int r_ld = tid>>2, c_ld=(tid&3)*8;   // cp.async: 4 threads/row, 8 halves each

  int nch = Min>>5;
  for(int ch=0; ch<nch; ch++){
    int k0=ch<<5;
    #pragma unroll
    for(int it=0;it<2;it++){
      int rr = r_ld + it*64;
      uint32_t soff=(uint32_t)(rr*PADH+c_ld)*2;
      cpa16f(sAh+soff, &Ah[(size_t)(bm+rr)*Min+k0+c_ld]);
      cpa16f(sAl+soff, &Al[(size_t)(bm+rr)*Min+k0+c_ld]);
      cpa16f(sBh+soff, &Bh[(size_t)(bn+rr)*Min+k0+c_ld]);
      cpa16f(sBl+soff, &Bl[(size_t)(bn+rr)*Min+k0+c_ld]);
    }
    CPA_COMMIT();
    CPA_WAIT0();
    __syncthreads();

    #pragma unroll
    for(int kst=0;kst<2;kst++){
      uint32_t kb = (uint32_t)kst*32;   // 16 halves
      uint32_t afh[2][4], afl[2][4];
      LDSM4(afh[0], sAh + a_off[0] + kb);
      LDSM4(afh[1], sAh + a_off[1] + kb);
      LDSM4(afl[0], sAl + a_off[0] + kb);
      LDSM4(afl[1], sAl + a_off[1] + kb);
      #pragma unroll
      for(int p=0;p<4;p++){
        uint32_t bh4[4], bl4[4];
        LDSM4(bh4, sBh + b_off[p] + kb);
        LDSM4(bl4, sBl + b_off[p] + kb);
        int nf0=2*p, nf1=2*p+1;
        #pragma unroll
        for(int mf=0;mf<2;mf++){
          mma16(acc[mf][nf0], afh[mf], bh4[0], bh4[1]);
          mma16(acc[mf][nf0], afh[mf], bl4[0], bl4[1]);
          mma16(acc[mf][nf0], afl[mf], bh4[0], bh4[1]);
          mma16(acc[mf][nf1], afh[mf], bh4[2], bh4[3]);
          mma16(acc[mf][nf1], afh[mf], bl4[2], bl4[3]);
          mma16(acc[mf][nf1], afl[mf], bh4[2], bh4[3]);
        }
      }
    }
    __syncthreads();
  }

  // epilogue: bias + relu, unconditional float2 stores (C is row-padded)
  #pragma unroll
  for(int mf=0;mf<2;mf++){
    int row0 = bm + wm*32 + mf*16 + (lane>>2);
    #pragma unroll
    for(int nf=0;nf<8;nf++){
      int col = bn + wn*64 + nf*8 + (lane&3)*2;
      float b0v=bias[col], b1v=bias[col+1];
      float2 v0; v0.x=fmaxf(acc[mf][nf][0]+b0v,0.f); v0.y=fmaxf(acc[mf][nf][1]+b1v,0.f);
      *(float2*)&C[(size_t)row0*Kout+col]=v0;
      float2 v1; v1.x=fmaxf(acc[mf][nf][2]+b0v,0.f); v1.y=fmaxf(acc[mf][nf][3]+b1v,0.f);
      *(float2*)&C[(size_t)(row0+8)*Kout+col]=v1;
    }
  }
}
#define MMA_SMEM (4*CHB2)

// ---------------- softmax + argmax (warp per row of 512, float4 IO) ----------------
__global__ void k_softmax(const float* __restrict__ h, float* __restrict__ S){
  int warp=blockIdx.x*(blockDim.x>>5)+(threadIdx.x>>5);
  int lane=threadIdx.x&31;
  if(warp>=NN) return;
  const float4* row4=(const float4*)(h+(size_t)warp*CC);
  float4 v[4];
  #pragma unroll
  for(int c=0;c<4;c++) v[c]=row4[c*32+lane];
  float m=-3.4e38f; int am=0;
  #pragma unroll
  for(int c=0;c<4;c++){
    float* f=(float*)&v[c];
    #pragma unroll
    for(int j=0;j<4;j++){
      int col=c*128+lane*4+j;
      if(f[j]>m){m=f[j];am=col;}
    }
  }
  #pragma unroll
  for(int off=16;off>0;off>>=1){
    float om=__shfl_down_sync(0xffffffffu,m,off);
    int   oa=__shfl_down_sync(0xffffffffu,am,off);
    if(om>m || (om==m && oa<am)){m=om;am=oa;}
  }
  m=__shfl_sync(0xffffffffu,m,0);
  am=__shfl_sync(0xffffffffu,am,0);
  float s=0.f;
  #pragma unroll
  for(int c=0;c<4;c++){
    float* f=(float*)&v[c];
    #pragma unroll
    for(int j=0;j<4;j++){ f[j]=expf(f[j]-m); s+=f[j]; }
  }
  #pragma unroll
  for(int off=16;off>0;off>>=1) s+=__shfl_down_sync(0xffffffffu,s,off);
  s=__shfl_sync(0xffffffffu,s,0);
  float invs=1.f/s;
  float4* so4=(float4*)(S+(size_t)warp*CC);
  #pragma unroll
  for(int c=0;c<4;c++){
    float* f=(float*)&v[c];
    #pragma unroll
    for(int j=0;j<4;j++) f[j]*=invs;
    so4[c*32+lane]=v[c];
  }
  if(lane==0) g_cluster[warp]=am;
}

// ---------------- score branch ----------------
__global__ void k_degs(){
  int i=blockIdx.x*blockDim.x+threadIdx.x;
  if(i>=NN) return;
  int ci=g_cluster[i];
  int s=g_rowptr[i], e=g_rowptr[i+1], cnt=0;
  for(int t=s;t<e;t++) cnt += (g_cluster[g_csrsrc[t]]==ci) ? 1 : 0;
  float w=rsqrtf((float)cnt+1.0f);
  g_invs[i]=w;
  g_hs[i]=w*g_hs[i];
  if(cnt>0) atomicAdd(&g_cintra[ci],cnt);
}

__global__ void k_score(const float* __restrict__ bs, float* __restrict__ out){
  int i=blockIdx.x*blockDim.x+threadIdx.x;
  if(i>=NN) return;
  int ci=g_cluster[i];
  bool iok = g_cintra[ci]>0;
  int s=g_rowptr[i], e=g_rowptr[i+1];
  float sum=0.f;
  for(int t=s;t<e;t++){
    int sn=g_csrsrc[t];
    int cs=g_cluster[sn];
    if(cs==ci) sum += g_hs[sn];
    else if(iok && g_cintra[cs]>0) out[OFF_ADJ + cs*CC + ci]=1.0f;
  }
  float w=g_invs[i];
  float sc=tanhf(w*(sum + g_hs[i]) + bs[0]);
  unsigned int key=((unsigned int)fenc(sc))^0x80000000u;
  unsigned long long pack=((unsigned long long)key<<32)|(unsigned int)(NN-1-i);
  atomicMax(&g_segpack[ci], pack);
}

// ---------------- outputs ----------------
__global__ void k_newx(const float* __restrict__ x, float* __restrict__ out){
  int c=blockIdx.x;
  int t=threadIdx.x;
  __shared__ float alpha; __shared__ int idx;
  if(t==0){
    unsigned long long p=g_segpack[c];
    int sidx = NN-1-(int)(unsigned int)(p&0xffffffffu);
    idx = min(max(sidx,0), NN-1);
    float sc = fdec((int)((unsigned int)(p>>32)^0x80000000u));
    alpha = (g_cintra[c]>0) ? sc : 0.f;
  }
  __syncthreads();
  out[OFF_NEWX + c*FF + t] = x[(size_t)idx*FF + t]*alpha;
}

// ---------------- launch ----------------
extern "C" void kernel_launch(void* const* d_in, const int* in_sizes, int n_in,
                              void* d_out, int out_size)
{
  const float* x  =(const float*)d_in[0];
  const int*   ei =(const int*)  d_in[1];
  const float* W1 =(const float*)d_in[3];
  const float* b1 =(const float*)d_in[4];
  const float* W2 =(const float*)d_in[5];
  const float* b2 =(const float*)d_in[6];
  const float* W3 =(const float*)d_in[7];
  const float* b3 =(const float*)d_in[8];
  const float* Wsm=(const float*)d_in[9];
  const float* bs =(const float*)d_in[10];
  float* out=(float*)d_out;

  const int* srcp=ei;
  const int* dstp=ei+EE;

  float *p_h;
  __half *p_ah,*p_al,*p_wh,*p_wl;
  cudaGetSymbolAddress((void**)&p_h,  g_h);
  cudaGetSymbolAddress((void**)&p_ah, g_Ahh);
  cudaGetSymbolAddress((void**)&p_al, g_All);
  cudaGetSymbolAddress((void**)&p_wh, g_Wth);
  cudaGetSymbolAddress((void**)&p_wl, g_Wtl);

  cudaFuncSetAttribute(k_mma, cudaFuncAttributeMaxDynamicSharedMemorySize, MMA_SMEM);

  const int TB=256;
  const int gN=(NN+TB-1)/TB;            // 196
  const int gE=(EE+TB-1)/TB;
  const int gW=(NN+7)/8;
  const int gM=NP/128;                  // 391
  const int gI=(CC*CC+CC+TB-1)/TB;

  // graph prep
  k_init<<<gI,TB>>>(out);
  k_deg<<<gE,TB>>>(dstp);
  k_scan1<<<gN,TB>>>();
  k_scan2<<<1,256>>>(gN);
  k_scan3p<<<gN,TB>>>();
  k_scatter<<<gE,TB>>>(srcp,dstp);
  k_wsplit3<<<(WTOT+TB-1)/TB,TB>>>(W1,W2,W3);

  // layer 1: F=128 -> 256 (hs fused into agg)
  k_agg<1,true><<<gW,TB>>>(x,p_ah,p_al,Wsm);
  k_mma<<<dim3(2,gM),256,MMA_SMEM>>>(p_ah,p_al,p_wh+WOFF1,p_wl+WOFF1,b1,p_h,128,256);

  // layer 2: 256 -> 256
  k_agg<2,false><<<gW,TB>>>(p_h,p_ah,p_al,Wsm);
  k_mma<<<dim3(2,gM),256,MMA_SMEM>>>(p_ah,p_al,p_wh+WOFF2,p_wl+WOFF2,b2,p_h,256,256);

  // layer 3: 256 -> 512
  k_agg<2,false><<<gW,TB>>>(p_h,p_ah,p_al,Wsm);
  k_mma<<<dim3(4,gM),256,MMA_SMEM>>>(p_ah,p_al,p_wh+WOFF3,p_wl+WOFF3,b3,p_h,256,512);

  // softmax S + hard cluster assignment
  k_softmax<<<gW,TB>>>(p_h, out+OFF_S);

  // score branch (score+segreduce+adj fused)
  k_degs<<<gN,TB>>>();
  k_score<<<gN,TB>>>(bs,out);

  // pooled features
  k_newx<<<CC,FF>>>(x,out);
}

// round 13
// speedup vs baseline: 1.4492x; 1.0239x over previous
#include <cuda_runtime.h>
#include <cuda_fp16.h>
#include <math.h>
#include <limits.h>
#include <stdint.h>

#define NN 50000
#define NP 50048          // NN padded to multiple of 128
#define FF 128
#define CC 512
#define EE 800000
#define HH 256

#define OFF_NEWX 0
#define OFF_ADJ  (CC*FF)
#define OFF_BATCH (OFF_ADJ + CC*CC)
#define OFF_S    (OFF_BATCH + CC)

// weight slab offsets (elements) in g_Wth/g_Wtl
#define WOFF1 0
#define WOFF2 (128*256)
#define WOFF3 (128*256+256*256)
#define WTOT  (128*256+256*256+256*512)

// ---------------- device scratch (static, no allocations) ----------------
static __device__ float  g_h[(size_t)NP*CC];     // GEMM outputs (padded rows)
static __device__ __half g_Ahh[(size_t)NP*HH];   // fp16-hi aggregated features
static __device__ __half g_All[(size_t)NP*HH];   // fp16-lo aggregated features
static __device__ __half g_Wth[WTOT];            // transposed fp16-hi weights (all layers)
static __device__ __half g_Wtl[WTOT];            // transposed fp16-lo weights
static __device__ int    g_rowptr[NN+1];
static __device__ int    g_deg[NN];
static __device__ int    g_cursor[NN];
static __device__ int    g_csrsrc[EE];
static __device__ float  g_inv[NN];
static __device__ float  g_hs[NN];               // hs, later overwritten with z=invs*hs
static __device__ float  g_invs[NN];
static __device__ int    g_cluster[NN];
static __device__ unsigned long long g_segpack[CC];
static __device__ int    g_cintra[CC];
static __device__ int    g_part[256];

// ---------------- helpers ----------------
__device__ __forceinline__ int fenc(float f){ int i=__float_as_int(f); return i<0 ? (i^0x7FFFFFFF) : i; }
__device__ __forceinline__ float fdec(int i){ return __int_as_float(i<0 ? (i^0x7FFFFFFF) : i); }

__device__ __forceinline__ uint32_t smem_u32(const void* p){
  uint32_t a; asm("{ .reg .u64 t; cvta.to.shared.u64 t, %1; cvt.u32.u64 %0, t; }":"=r"(a):"l"(p)); return a;
}

__device__ __forceinline__ void cpa16f(uint32_t s, const void* g){
  asm volatile("cp.async.ca.shared.global [%0], [%1], 16;"::"r"(s),"l"(g));
}
#define CPA_COMMIT() asm volatile("cp.async.commit_group;")
#define CPA_WAIT1()  asm volatile("cp.async.wait_group 1;":::"memory")
#define CPA_WAIT0()  asm volatile("cp.async.wait_group 0;":::"memory")

#define LDSM4(d, addr) asm volatile( \
    "ldmatrix.sync.aligned.m8n8.x4.shared.b16 {%0,%1,%2,%3},[%4];" \
    : "=r"((d)[0]),"=r"((d)[1]),"=r"((d)[2]),"=r"((d)[3]) : "r"(addr))

// mma.sync m16n8k16 fp16 -> fp32: D += A*B (row.col)
__device__ __forceinline__ void mma16(float* c, const uint32_t* a, uint32_t b0, uint32_t b1){
  asm volatile(
    "mma.sync.aligned.m16n8k16.row.col.f32.f16.f16.f32 "
    "{%0,%1,%2,%3},{%4,%5,%6,%7},{%8,%9},{%0,%1,%2,%3};"
    : "+f"(c[0]),"+f"(c[1]),"+f"(c[2]),"+f"(c[3])
    : "r"(a[0]),"r"(a[1]),"r"(a[2]),"r"(a[3]),"r"(b0),"r"(b1));
}

// fp16 hi/lo split of an fp32 value
__device__ __forceinline__ void h_split(float f, __half& hi, __half& lo){
  hi=__float2half_rn(f);
  lo=__float2half_rn(f-__half2float(hi));
}

// ---------------- setup kernels ----------------
__global__ void k_init(float* __restrict__ out){
  int i=blockIdx.x*blockDim.x+threadIdx.x;
  if(i<NN) g_deg[i]=0;
  if(i<CC){ g_cintra[i]=0; g_segpack[i]=0ull; }
  if(i<CC*CC+CC) out[OFF_ADJ+i]=0.f;
}

__global__ void k_deg(const int* __restrict__ dst){
  int e=blockIdx.x*blockDim.x+threadIdx.x;
  if(e<EE) atomicAdd(&g_deg[dst[e]],1);
}

// 3-phase exclusive scan of g_deg -> g_rowptr
__global__ void k_scan1(){
  int b=blockIdx.x, t=threadIdx.x, i=b*256+t;
  int v=(i<NN)?g_deg[i]:0;
  int x=v;
  #pragma unroll
  for(int off=1;off<32;off<<=1){
    int y=__shfl_up_sync(0xffffffffu,x,off);
    if((t&31)>=off) x+=y;
  }
  __shared__ int ws[8];
  if((t&31)==31) ws[t>>5]=x;
  __syncthreads();
  if(t==0){ int s=0; for(int j=0;j<8;j++){int tmp=ws[j]; ws[j]=s; s+=tmp;} g_part[b]=s; }
  __syncthreads();
  if(i<NN) g_rowptr[i]= x - v + ws[t>>5];
}
__global__ void k_scan2(int nblk){
  int t=threadIdx.x;
  int v=(t<nblk)?g_part[t]:0;
  int x=v;
  #pragma unroll
  for(int off=1;off<32;off<<=1){
    int y=__shfl_up_sync(0xffffffffu,x,off);
    if((t&31)>=off) x+=y;
  }
  __shared__ int wb[8];
  if((t&31)==31) wb[t>>5]=x;
  __syncthreads();
  if(t==0){ int s=0; for(int j=0;j<8;j++){int tmp=wb[j]; wb[j]=s; s+=tmp;} }
  __syncthreads();
  int excl = x - v + wb[t>>5];
  if(t<nblk) g_part[t]=excl;
  if(t==nblk-1) g_rowptr[NN]=excl+v;
}
__global__ void k_scan3p(){
  int i=blockIdx.x*blockDim.x+threadIdx.x;
  if(i>=NN) return;
  int v=g_rowptr[i]+g_part[i>>8];
  g_rowptr[i]=v;
  g_cursor[i]=v;
  g_inv[i]=rsqrtf((float)g_deg[i]+1.0f);
}

__global__ void k_scatter(const int* __restrict__ src, const int* __restrict__ dst){
  int e=blockIdx.x*blockDim.x+threadIdx.x;
  if(e>=EE) return;
  int d=dst[e];
  int p=atomicAdd(&g_cursor[d],1);
  g_csrsrc[p]=src[e];
}

// ---------------- aggregation with fused inv scaling + fp16 split (+ optional hs) ----------------
template<int V, bool HS>
__global__ void k_agg(const float* __restrict__ h, __half* __restrict__ ah, __half* __restrict__ al,
                      const float* __restrict__ Wsm){
  int warp=blockIdx.x*(blockDim.x>>5) + (threadIdx.x>>5);
  int lane=threadIdx.x&31;
  if(warp>=NN) return;
  const float4* h4=(const float4*)h;
  size_t base=(size_t)warp*(32*V);
  float wi=g_inv[warp];
  float4 acc[V];
  #pragma unroll
  for(int v=0;v<V;v++){
    float4 q=h4[base+v*32+lane];
    if(HS && v==0){
      float4 w=((const float4*)Wsm)[lane];
      float d=q.x*w.x+q.y*w.y+q.z*w.z+q.w*w.w;
      #pragma unroll
      for(int off=16;off>0;off>>=1) d+=__shfl_down_sync(0xffffffffu,d,off);
      if(lane==0) g_hs[warp]=d;
    }
    acc[v].x=q.x*wi; acc[v].y=q.y*wi; acc[v].z=q.z*wi; acc[v].w=q.w*wi;
  }
  int s=g_rowptr[warp], e=g_rowptr[warp+1];
  for(int t=s;t<e;t++){
    int src=g_csrsrc[t];
    float ws=g_inv[src];
    const float4* r=h4+(size_t)src*(32*V);
    #pragma unroll
    for(int v=0;v<V;v++){
      float4 q=r[v*32+lane];
      acc[v].x=fmaf(q.x,ws,acc[v].x);
      acc[v].y=fmaf(q.y,ws,acc[v].y);
      acc[v].z=fmaf(q.z,ws,acc[v].z);
      acc[v].w=fmaf(q.w,ws,acc[v].w);
    }
  }
  #pragma unroll
  for(int v=0;v<V;v++){
    float f[4]={acc[v].x*wi, acc[v].y*wi, acc[v].z*wi, acc[v].w*wi};
    __half hv[4], lv[4];
    h_split(f[0],hv[0],lv[0]);
    h_split(f[1],hv[1],lv[1]);
    h_split(f[2],hv[2],lv[2]);
    h_split(f[3],hv[3],lv[3]);
    size_t off=(size_t)warp*(128*V) + v*128 + lane*4;
    *(uint2*)&ah[off]=*(uint2*)hv;
    *(uint2*)&al[off]=*(uint2*)lv;
  }
}

// transpose + split all three weight matrices (fp16 hi/lo)
__global__ void k_wsplit3(const float* __restrict__ W1, const float* __restrict__ W2,
                          const float* __restrict__ W3){
  int idx=blockIdx.x*blockDim.x+threadIdx.x;
  if(idx>=WTOT) return;
  const float* W; int Min,Kout,off,li;
  if(idx<WOFF2){ W=W1; Min=128; Kout=256; off=WOFF1; li=idx; }
  else if(idx<WOFF3){ W=W2; Min=256; Kout=256; off=WOFF2; li=idx-WOFF2; }
  else { W=W3; Min=256; Kout=512; off=WOFF3; li=idx-WOFF3; }
  int m=li/Kout, nk=li-m*Kout;
  __half hi,lo;
  h_split(W[li],hi,lo);
  g_Wth[off+nk*Min+m]=hi;
  g_Wtl[off+nk*Min+m]=lo;
}

// ---------------- fp16 split-3 mma.sync GEMM (m16n8k16), double-buffered cp.async ----------------
// CTA tile 128(m) x 128(n); 8 warps 4m x 2n; warp tile 32x64; K chunks of 32 (2 ksteps of 16).
#define PADH 40               // halves per smem row (80B stride)
#define CHH (128*PADH)        // halves per slab
#define CHB2 (CHH*2)          // bytes per slab
#define BUFB (4*CHB2)         // bytes per buffer (4 slabs)
__global__ __launch_bounds__(256,2) void k_mma(
    const __half* __restrict__ Ah, const __half* __restrict__ Al,
    const __half* __restrict__ Bh, const __half* __restrict__ Bl,
    const float* __restrict__ bias, float* __restrict__ C,
    int Min, int Kout)
{
  extern __shared__ __half smh[];
  int tid=threadIdx.x, lane=tid&31, wid=tid>>5;
  int wm = wid&3, wn = wid>>2;         // 4x2 warp grid
  int bm = blockIdx.y*128, bn = blockIdx.x*128;

  uint32_t s_base = smem_u32(smh);

  float acc[2][8][4];
  #pragma unroll
  for(int a=0;a<2;a++)
    #pragma unroll
    for(int b=0;b<8;b++)
      #pragma unroll
      for(int c=0;c<4;c++) acc[a][b][c]=0.f;

  // ldmatrix per-lane base offsets (bytes within a slab)
  int g=lane>>3, lr=lane&7;
  uint32_t a_off[2], b_off[4];
  #pragma unroll
  for(int mf=0;mf<2;mf++)
    a_off[mf]=(uint32_t)((wm*32+mf*16+(g&1)*8+lr)*PADH + (g>>1)*8)*2;
  #pragma unroll
  for(int p=0;p<4;p++)
    b_off[p]=(uint32_t)((wn*64+p*16+(g>>1)*8+lr)*PADH + (g&1)*8)*2;

  int r_ld = tid>>2, c_ld=(tid&3)*8;   // cp.async: 4 threads/row, 8 halves each

  auto issue=[&](int ch, int b){
    int k0=ch<<5;
    uint32_t s0 = s_base + (uint32_t)b*BUFB;
    #pragma unroll
    for(int it=0;it<2;it++){
      int rr = r_ld + it*64;
      uint32_t soff=(uint32_t)(rr*PADH+c_ld)*2;
      cpa16f(s0 +          soff, &Ah[(size_t)(bm+rr)*Min+k0+c_ld]);
      cpa16f(s0 +   CHB2 + soff, &Al[(size_t)(bm+rr)*Min+k0+c_ld]);
      cpa16f(s0 + 2*CHB2 + soff, &Bh[(size_t)(bn+rr)*Min+k0+c_ld]);
      cpa16f(s0 + 3*CHB2 + soff, &Bl[(size_t)(bn+rr)*Min+k0+c_ld]);
    }
    CPA_COMMIT();
  };

  int nch = Min>>5;
  issue(0,0);
  for(int ch=0; ch<nch; ch++){
    int b=ch&1;
    if(ch+1<nch){ issue(ch+1, b^1); CPA_WAIT1(); }
    else        { CPA_WAIT0(); }
    __syncthreads();

    uint32_t s0 = s_base + (uint32_t)b*BUFB;
    uint32_t sAh=s0, sAl=s0+CHB2, sBh=s0+2*CHB2, sBl=s0+3*CHB2;

    #pragma unroll
    for(int kst=0;kst<2;kst++){
      uint32_t kb = (uint32_t)kst*32;   // 16 halves
      uint32_t afh[2][4], afl[2][4];
      LDSM4(afh[0], sAh + a_off[0] + kb);
      LDSM4(afh[1], sAh + a_off[1] + kb);
      LDSM4(afl[0], sAl + a_off[0] + kb);
      LDSM4(afl[1], sAl + a_off[1] + kb);
      #pragma unroll
      for(int p=0;p<4;p++){
        uint32_t bh4[4], bl4[4];
        LDSM4(bh4, sBh + b_off[p] + kb);
        LDSM4(bl4, sBl + b_off[p] + kb);
        int nf0=2*p, nf1=2*p+1;
        #pragma unroll
        for(int mf=0;mf<2;mf++){
          mma16(acc[mf][nf0], afh[mf], bh4[0], bh4[1]);
          mma16(acc[mf][nf0], afh[mf], bl4[0], bl4[1]);
          mma16(acc[mf][nf0], afl[mf], bh4[0], bh4[1]);
          mma16(acc[mf][nf1], afh[mf], bh4[2], bh4[3]);
          mma16(acc[mf][nf1], afh[mf], bl4[2], bl4[3]);
          mma16(acc[mf][nf1], afl[mf], bh4[2], bh4[3]);
        }
      }
    }
    __syncthreads();
  }

  // epilogue: bias + relu, unconditional float2 stores (C is row-padded)
  #pragma unroll
  for(int mf=0;mf<2;mf++){
    int row0 = bm + wm*32 + mf*16 + (lane>>2);
    #pragma unroll
    for(int nf=0;nf<8;nf++){
      int col = bn + wn*64 + nf*8 + (lane&3)*2;
      float b0v=bias[col], b1v=bias[col+1];
      float2 v0; v0.x=fmaxf(acc[mf][nf][0]+b0v,0.f); v0.y=fmaxf(acc[mf][nf][1]+b1v,0.f);
      *(float2*)&C[(size_t)row0*Kout+col]=v0;
      float2 v1; v1.x=fmaxf(acc[mf][nf][2]+b0v,0.f); v1.y=fmaxf(acc[mf][nf][3]+b1v,0.f);
      *(float2*)&C[(size_t)(row0+8)*Kout+col]=v1;
    }
  }
}
#define MMA_SMEM (2*BUFB)

// ---------------- softmax + argmax (warp per row of 512, float4 IO) ----------------
__global__ void k_softmax(const float* __restrict__ h, float* __restrict__ S){
  int warp=blockIdx.x*(blockDim.x>>5)+(threadIdx.x>>5);
  int lane=threadIdx.x&31;
  if(warp>=NN) return;
  const float4* row4=(const float4*)(h+(size_t)warp*CC);
  float4 v[4];
  #pragma unroll
  for(int c=0;c<4;c++) v[c]=row4[c*32+lane];
  float m=-3.4e38f; int am=0;
  #pragma unroll
  for(int c=0;c<4;c++){
    float* f=(float*)&v[c];
    #pragma unroll
    for(int j=0;j<4;j++){
      int col=c*128+lane*4+j;
      if(f[j]>m){m=f[j];am=col;}
    }
  }
  #pragma unroll
  for(int off=16;off>0;off>>=1){
    float om=__shfl_down_sync(0xffffffffu,m,off);
    int   oa=__shfl_down_sync(0xffffffffu,am,off);
    if(om>m || (om==m && oa<am)){m=om;am=oa;}
  }
  m=__shfl_sync(0xffffffffu,m,0);
  am=__shfl_sync(0xffffffffu,am,0);
  float s=0.f;
  #pragma unroll
  for(int c=0;c<4;c++){
    float* f=(float*)&v[c];
    #pragma unroll
    for(int j=0;j<4;j++){ f[j]=expf(f[j]-m); s+=f[j]; }
  }
  #pragma unroll
  for(int off=16;off>0;off>>=1) s+=__shfl_down_sync(0xffffffffu,s,off);
  s=__shfl_sync(0xffffffffu,s,0);
  float invs=1.f/s;
  float4* so4=(float4*)(S+(size_t)warp*CC);
  #pragma unroll
  for(int c=0;c<4;c++){
    float* f=(float*)&v[c];
    #pragma unroll
    for(int j=0;j<4;j++) f[j]*=invs;
    so4[c*32+lane]=v[c];
  }
  if(lane==0) g_cluster[warp]=am;
}

// ---------------- score branch: 4 threads per node ----------------
__global__ void k_degs(){
  int gt=blockIdx.x*blockDim.x+threadIdx.x;
  int i=gt>>2, sub=gt&3;
  if(i>=NN) return;
  int ci=g_cluster[i];
  int s=g_rowptr[i], e=g_rowptr[i+1], cnt=0;
  for(int t=s+sub;t<e;t+=4) cnt += (g_cluster[g_csrsrc[t]]==ci) ? 1 : 0;
  cnt += __shfl_down_sync(0xffffffffu,cnt,2,4);
  cnt += __shfl_down_sync(0xffffffffu,cnt,1,4);
  if(sub==0){
    float w=rsqrtf((float)cnt+1.0f);
    g_invs[i]=w;
    g_hs[i]=w*g_hs[i];
    if(cnt>0) atomicAdd(&g_cintra[ci],cnt);
  }
}

__global__ void k_score(const float* __restrict__ bs, float* __restrict__ out){
  int gt=blockIdx.x*blockDim.x+threadIdx.x;
  int i=gt>>2, sub=gt&3;
  if(i>=NN) return;
  int ci=g_cluster[i];
  bool iok = g_cintra[ci]>0;
  int s=g_rowptr[i], e=g_rowptr[i+1];
  float sum=0.f;
  for(int t=s+sub;t<e;t+=4){
    int sn=g_csrsrc[t];
    int cs=g_cluster[sn];
    if(cs==ci) sum += g_hs[sn];
    else if(iok && g_cintra[cs]>0) out[OFF_ADJ + cs*CC + ci]=1.0f;
  }
  sum += __shfl_down_sync(0xffffffffu,sum,2,4);
  sum += __shfl_down_sync(0xffffffffu,sum,1,4);
  if(sub==0){
    float w=g_invs[i];
    float sc=tanhf(w*(sum + g_hs[i]) + bs[0]);
    unsigned int key=((unsigned int)fenc(sc))^0x80000000u;
    unsigned long long pack=((unsigned long long)key<<32)|(unsigned int)(NN-1-i);
    atomicMax(&g_segpack[ci], pack);
  }
}

// ---------------- outputs ----------------
__global__ void k_newx(const float* __restrict__ x, float* __restrict__ out){
  int c=blockIdx.x;
  int t=threadIdx.x;
  __shared__ float alpha; __shared__ int idx;
  if(t==0){
    unsigned long long p=g_segpack[c];
    int sidx = NN-1-(int)(unsigned int)(p&0xffffffffu);
    idx = min(max(sidx,0), NN-1);
    float sc = fdec((int)((unsigned int)(p>>32)^0x80000000u));
    alpha = (g_cintra[c]>0) ? sc : 0.f;
  }
  __syncthreads();
  out[OFF_NEWX + c*FF + t] = x[(size_t)idx*FF + t]*alpha;
}

// ---------------- launch ----------------
extern "C" void kernel_launch(void* const* d_in, const int* in_sizes, int n_in,
                              void* d_out, int out_size)
{
  const float* x  =(const float*)d_in[0];
  const int*   ei =(const int*)  d_in[1];
  const float* W1 =(const float*)d_in[3];
  const float* b1 =(const float*)d_in[4];
  const float* W2 =(const float*)d_in[5];
  const float* b2 =(const float*)d_in[6];
  const float* W3 =(const float*)d_in[7];
  const float* b3 =(const float*)d_in[8];
  const float* Wsm=(const float*)d_in[9];
  const float* bs =(const float*)d_in[10];
  float* out=(float*)d_out;

  const int* srcp=ei;
  const int* dstp=ei+EE;

  float *p_h;
  __half *p_ah,*p_al,*p_wh,*p_wl;
  cudaGetSymbolAddress((void**)&p_h,  g_h);
  cudaGetSymbolAddress((void**)&p_ah, g_Ahh);
  cudaGetSymbolAddress((void**)&p_al, g_All);
  cudaGetSymbolAddress((void**)&p_wh, g_Wth);
  cudaGetSymbolAddress((void**)&p_wl, g_Wtl);

  cudaFuncSetAttribute(k_mma, cudaFuncAttributeMaxDynamicSharedMemorySize, MMA_SMEM);

  const int TB=256;
  const int gN=(NN+TB-1)/TB;            // 196
  const int gE=(EE+TB-1)/TB;
  const int gW=(NN+7)/8;
  const int g4=(NN*4+TB-1)/TB;          // 4-threads-per-node kernels
  const int gM=NP/128;                  // 391
  const int gI=(CC*CC+CC+TB-1)/TB;

  // graph prep
  k_init<<<gI,TB>>>(out);
  k_deg<<<gE,TB>>>(dstp);
  k_scan1<<<gN,TB>>>();
  k_scan2<<<1,256>>>(gN);
  k_scan3p<<<gN,TB>>>();
  k_scatter<<<gE,TB>>>(srcp,dstp);
  k_wsplit3<<<(WTOT+TB-1)/TB,TB>>>(W1,W2,W3);

  // layer 1: F=128 -> 256 (hs fused into agg)
  k_agg<1,true><<<gW,TB>>>(x,p_ah,p_al,Wsm);
  k_mma<<<dim3(2,gM),256,MMA_SMEM>>>(p_ah,p_al,p_wh+WOFF1,p_wl+WOFF1,b1,p_h,128,256);

  // layer 2: 256 -> 256
  k_agg<2,false><<<gW,TB>>>(p_h,p_ah,p_al,Wsm);
  k_mma<<<dim3(2,gM),256,MMA_SMEM>>>(p_ah,p_al,p_wh+WOFF2,p_wl+WOFF2,b2,p_h,256,256);

  // layer 3: 256 -> 512
  k_agg<2,false><<<gW,TB>>>(p_h,p_ah,p_al,Wsm);
  k_mma<<<dim3(4,gM),256,MMA_SMEM>>>(p_ah,p_al,p_wh+WOFF3,p_wl+WOFF3,b3,p_h,256,512);

  // softmax S + hard cluster assignment
  k_softmax<<<gW,TB>>>(p_h, out+OFF_S);

  // score branch (4 threads per node)
  k_degs<<<g4,TB>>>();
  k_score<<<g4,TB>>>(bs,out);

  // pooled features
  k_newx<<<CC,FF>>>(x,out);
}